// round 1
// baseline (speedup 1.0000x reference)
#include <cuda_runtime.h>
#include <cstdint>
#include <cstddef>

// ---------------------------------------------------------------------------
// LongTermMemoryMLP: out = (relu(relu(q@W0^T + b0)@W1^T + b1))@W2^T + b2
// per batch b (8 batches). Shapes per batch:
//   L0: M=4096 N=1024 K=512   (relu)
//   L1: M=4096 N=1024 K=1024  (relu)
//   L2: M=4096 N=512  K=1024  (no relu)
// Strategy (round 0): TF32 mma.sync tiled GEMM, 128x128x16 blocktile,
// 256 threads (8 warps, 2x4 -> warp tile 64x32), fused bias+relu epilogue.
// Activations staged in __device__ scratch (no allocations).
// ---------------------------------------------------------------------------

#define BM 128
#define BN 128
#define BKT 16
#define PAD 8   // row stride 136 words: (136 mod 32)=8 -> conflict-free frag loads

// Layer activation scratch: 8*4096*1024 floats = 128MB each.
__device__ float g_h0[8u * 4096u * 1024u];
__device__ float g_h1[8u * 4096u * 1024u];

__device__ __forceinline__ uint32_t f2tf(float x) {
    uint32_t r;
    asm("cvt.rna.tf32.f32 %0, %1;" : "=r"(r) : "f"(x));
    return r;
}

template <int KDIM, bool RELU>
__global__ __launch_bounds__(256, 2)
void gemm_tf32_bias_act(const float* __restrict__ A,   // [B, M, KDIM]
                        const float* __restrict__ W,   // [B, N, KDIM]
                        const float* __restrict__ bias,// [B, N]
                        float* __restrict__ C,         // [B, M, N]
                        int M, int N) {
    const int bz = blockIdx.z;
    A    += (size_t)bz * M * KDIM;
    W    += (size_t)bz * N * KDIM;
    bias += (size_t)bz * N;
    C    += (size_t)bz * M * N;

    const int m0 = blockIdx.x * BM;
    const int n0 = blockIdx.y * BN;

    __shared__ uint32_t As[BKT][BM + PAD];
    __shared__ uint32_t Bs[BKT][BN + PAD];

    const int tid  = threadIdx.x;
    const int lane = tid & 31;
    const int warp = tid >> 5;
    const int wm   = (warp & 1) * 64;   // warp M offset in tile
    const int wn   = (warp >> 1) * 32;  // warp N offset in tile

    float acc[4][4][4];
#pragma unroll
    for (int i = 0; i < 4; i++)
#pragma unroll
        for (int j = 0; j < 4; j++)
#pragma unroll
            for (int r = 0; r < 4; r++) acc[i][j][r] = 0.0f;

    const int ldr = tid >> 2;        // 0..63 : row within tile (per pass)
    const int ldk = (tid & 3) * 4;   // 0,4,8,12 : k offset (float4 chunk)

    const int kl4 = lane & 3;   // k index within mma frag
    const int lg  = lane >> 2;  // group id (row/col within frag)

    for (int k0 = 0; k0 < KDIM; k0 += BKT) {
        // --- global -> shared (transposed, converted to tf32) ---
#pragma unroll
        for (int p = 0; p < 2; p++) {
            const int row = ldr + p * 64;
            float4 va = *(const float4*)(A + (size_t)(m0 + row) * KDIM + k0 + ldk);
            As[ldk + 0][row] = f2tf(va.x);
            As[ldk + 1][row] = f2tf(va.y);
            As[ldk + 2][row] = f2tf(va.z);
            As[ldk + 3][row] = f2tf(va.w);
            float4 vb = *(const float4*)(W + (size_t)(n0 + row) * KDIM + k0 + ldk);
            Bs[ldk + 0][row] = f2tf(vb.x);
            Bs[ldk + 1][row] = f2tf(vb.y);
            Bs[ldk + 2][row] = f2tf(vb.z);
            Bs[ldk + 3][row] = f2tf(vb.w);
        }
        __syncthreads();

        // --- compute: 2 k-steps of 8, 4x4 mma grid per warp ---
#pragma unroll
        for (int kk = 0; kk < BKT; kk += 8) {
            uint32_t a[4][4];
            uint32_t bb[4][2];
#pragma unroll
            for (int mi = 0; mi < 4; mi++) {
                const int mrow = wm + mi * 16 + lg;
                a[mi][0] = As[kk + kl4][mrow];
                a[mi][1] = As[kk + kl4][mrow + 8];
                a[mi][2] = As[kk + kl4 + 4][mrow];
                a[mi][3] = As[kk + kl4 + 4][mrow + 8];
            }
#pragma unroll
            for (int ni = 0; ni < 4; ni++) {
                const int ncol = wn + ni * 8 + lg;
                bb[ni][0] = Bs[kk + kl4][ncol];
                bb[ni][1] = Bs[kk + kl4 + 4][ncol];
            }
#pragma unroll
            for (int mi = 0; mi < 4; mi++) {
#pragma unroll
                for (int ni = 0; ni < 4; ni++) {
                    asm("mma.sync.aligned.m16n8k8.row.col.f32.tf32.tf32.f32 "
                        "{%0,%1,%2,%3}, {%4,%5,%6,%7}, {%8,%9}, {%0,%1,%2,%3};"
                        : "+f"(acc[mi][ni][0]), "+f"(acc[mi][ni][1]),
                          "+f"(acc[mi][ni][2]), "+f"(acc[mi][ni][3])
                        : "r"(a[mi][0]), "r"(a[mi][1]), "r"(a[mi][2]), "r"(a[mi][3]),
                          "r"(bb[ni][0]), "r"(bb[ni][1]));
                }
            }
        }
        __syncthreads();
    }

    // --- epilogue: +bias, optional relu, store ---
#pragma unroll
    for (int mi = 0; mi < 4; mi++) {
        const int r0 = m0 + wm + mi * 16 + lg;
#pragma unroll
        for (int ni = 0; ni < 4; ni++) {
            const int col = n0 + wn + ni * 8 + 2 * (lane & 3);
            const float bv0 = bias[col];
            const float bv1 = bias[col + 1];
            float v0 = acc[mi][ni][0] + bv0;
            float v1 = acc[mi][ni][1] + bv1;
            float v2 = acc[mi][ni][2] + bv0;
            float v3 = acc[mi][ni][3] + bv1;
            if (RELU) {
                v0 = fmaxf(v0, 0.0f);
                v1 = fmaxf(v1, 0.0f);
                v2 = fmaxf(v2, 0.0f);
                v3 = fmaxf(v3, 0.0f);
            }
            *(float2*)(C + (size_t)r0 * N + col)       = make_float2(v0, v1);
            *(float2*)(C + (size_t)(r0 + 8) * N + col) = make_float2(v2, v3);
        }
    }
}

extern "C" void kernel_launch(void* const* d_in, const int* in_sizes, int n_in,
                              void* d_out, int out_size) {
    const float* q  = (const float*)d_in[0];  // [8,4096,512]
    const float* W0 = (const float*)d_in[1];  // [8,1024,512]
    const float* b0 = (const float*)d_in[2];  // [8,1024]
    const float* W1 = (const float*)d_in[3];  // [8,1024,1024]
    const float* b1 = (const float*)d_in[4];  // [8,1024]
    const float* W2 = (const float*)d_in[5];  // [8,512,1024]
    const float* b2 = (const float*)d_in[6];  // [8,512]
    float* out = (float*)d_out;               // [8,4096,512]

    float* h0 = nullptr;
    float* h1 = nullptr;
    cudaGetSymbolAddress((void**)&h0, g_h0);
    cudaGetSymbolAddress((void**)&h1, g_h1);

    const int B = 8, S = 4096;

    // L0: [S,512] @ [1024,512]^T -> [S,1024], relu
    {
        dim3 grid(S / BM, 1024 / BN, B);
        gemm_tf32_bias_act<512, true><<<grid, 256>>>(q, W0, b0, h0, S, 1024);
    }
    // L1: [S,1024] @ [1024,1024]^T -> [S,1024], relu
    {
        dim3 grid(S / BM, 1024 / BN, B);
        gemm_tf32_bias_act<1024, true><<<grid, 256>>>(h0, W1, b1, h1, S, 1024);
    }
    // L2: [S,1024] @ [512,1024]^T -> [S,512], no relu
    {
        dim3 grid(S / BM, 512 / BN, B);
        gemm_tf32_bias_act<1024, false><<<grid, 256>>>(h1, W2, b2, out, S, 512);
    }
}

// round 9
// speedup vs baseline: 1.6084x; 1.6084x over previous
#include <cuda_runtime.h>
#include <cstdint>
#include <cstddef>

// ---------------------------------------------------------------------------
// LongTermMemoryMLP on sm_103 (legacy tensor path — tcgen05 blocked by the
// harness's compute_103 virtual arch).
//   L0: [4096x512] @ [1024x512]^T  +b relu   (per batch, B=8)
//   L1: [4096x1024]@ [1024x1024]^T +b relu
//   L2: [4096x1024]@ [512x1024]^T  +b
// Round 5 design: mma.sync.m16n8k8.tf32 with
//   * cp.async.cg 3-stage gmem->smem pipeline (no transpose, no reg roundtrip)
//   * ldmatrix.x4 fragment loads (80B-padded rows -> conflict-free)
//   * tf32 pre-rounding outside the GEMM hot loop
// ---------------------------------------------------------------------------

#define BM 128
#define BN 128
#define BK 16
#define NSTAGE 3

#define ROWB 80                       // bytes per smem row (64B data + 16B pad)
#define A_BYTES (128 * ROWB)          // 10240
#define STAGE_SZ (2 * A_BYTES)        // 20480 (A then B)
#define SMEM_BYTES (NSTAGE * STAGE_SZ)  // 61440

// ---------------- scratch (no allocations allowed) ----------------
__device__ float g_qr[8u * 4096u * 512u];    //  64 MB tf32-rounded query
__device__ float g_w0[8u * 1024u * 512u];
__device__ float g_w1[8u * 1024u * 1024u];
__device__ float g_w2[8u * 512u * 1024u];
__device__ float g_h0[8u * 4096u * 1024u];   // rounded activations
__device__ float g_h1[8u * 4096u * 1024u];

// ---------------- helpers ----------------
__device__ __forceinline__ uint32_t smem_u32(const void* p) {
    uint32_t a;
    asm("{ .reg .u64 t; cvta.to.shared.u64 t, %1; cvt.u32.u64 %0, t; }" : "=r"(a) : "l"(p));
    return a;
}
__device__ __forceinline__ uint32_t f2tf(float x) {
    uint32_t r;
    asm("cvt.rna.tf32.f32 %0, %1;" : "=r"(r) : "f"(x));
    return r;
}
__device__ __forceinline__ void cp16(uint32_t dst, const void* src) {
    asm volatile("cp.async.cg.shared.global [%0], [%1], 16;" :: "r"(dst), "l"(src) : "memory");
}
__device__ __forceinline__ void ldsm4(uint32_t* r, uint32_t addr) {
    asm volatile("ldmatrix.sync.aligned.m8n8.x4.shared.b16 {%0,%1,%2,%3}, [%4];"
                 : "=r"(r[0]), "=r"(r[1]), "=r"(r[2]), "=r"(r[3]) : "r"(addr));
}
__device__ __forceinline__ void mma8(float* acc, const uint32_t* a, uint32_t b0, uint32_t b1) {
    asm("mma.sync.aligned.m16n8k8.row.col.f32.tf32.tf32.f32 "
        "{%0,%1,%2,%3}, {%4,%5,%6,%7}, {%8,%9}, {%0,%1,%2,%3};"
        : "+f"(acc[0]), "+f"(acc[1]), "+f"(acc[2]), "+f"(acc[3])
        : "r"(a[0]), "r"(a[1]), "r"(a[2]), "r"(a[3]), "r"(b0), "r"(b1));
}

// ---------------- main GEMM kernel ----------------
template <int KDIM, bool RELU>
__global__ __launch_bounds__(256, 2)
void gemm_tf32_ldsm(const float* __restrict__ A,     // [B*4096, KDIM] tf32-rounded
                    const float* __restrict__ W,     // [B*N,    KDIM] tf32-rounded
                    const float* __restrict__ bias,  // [B*N]
                    float* __restrict__ C,           // [B*4096, N]
                    int N) {
    extern __shared__ char smem[];
    const uint32_t sb = smem_u32(smem);

    const int tid  = threadIdx.x;
    const int lane = tid & 31;
    const int warp = tid >> 5;
    const int wm   = (warp & 1) * 64;
    const int wn   = (warp >> 1) * 32;

    const int bz  = blockIdx.z;
    const int m0g = bz * 4096 + blockIdx.x * BM;   // flattened A/C row base
    const int n0  = blockIdx.y * BN;
    const int n0g = bz * N + n0;                   // flattened W/bias row base

    const float* At = A + (size_t)m0g * KDIM;
    const float* Wt = W + (size_t)n0g * KDIM;

    // per-thread cp.async coordinates: 4 chunks of 16B (2 A-rows, 2 B-rows)
    const int crow = tid >> 2;       // 0..63
    const int ckc  = tid & 3;        // 16B chunk within 64B row
    const uint32_t cdstA = crow * ROWB + ckc * 16;
    const size_t   csrc  = (size_t)crow * KDIM + ckc * 4;

    // per-thread ldmatrix addresses (80B row stride -> conflict-free)
    const uint32_t aoff = (uint32_t)(wm + ((lane >> 3) & 1) * 8 + (lane & 7)) * ROWB
                        + (lane >> 4) * 16;                       // + mi*16*80 + kk*4
    const uint32_t boff = A_BYTES
                        + (uint32_t)(wn + (lane >> 4) * 8 + (lane & 7)) * ROWB
                        + ((lane >> 3) & 1) * 16;                 // + ni2*16*80 + kk*4

    float acc[4][4][4];
#pragma unroll
    for (int i = 0; i < 4; i++)
#pragma unroll
        for (int j = 0; j < 4; j++)
#pragma unroll
            for (int r = 0; r < 4; r++) acc[i][j][r] = 0.0f;

    constexpr int ITERS = KDIM / BK;

    // ---- prologue: fill first NSTAGE-1 stages ----
#pragma unroll
    for (int s = 0; s < NSTAGE - 1; ++s) {
        const uint32_t st = sb + s * STAGE_SZ;
        const int k0 = s * BK;
        cp16(st + cdstA,                 At + csrc + k0);
        cp16(st + cdstA + 64 * ROWB,     At + csrc + (size_t)64 * KDIM + k0);
        cp16(st + A_BYTES + cdstA,       Wt + csrc + k0);
        cp16(st + A_BYTES + cdstA + 64 * ROWB, Wt + csrc + (size_t)64 * KDIM + k0);
        asm volatile("cp.async.commit_group;" ::: "memory");
    }

    for (int it = 0; it < ITERS; ++it) {
        asm volatile("cp.async.wait_group %0;" :: "n"(NSTAGE - 2) : "memory");
        __syncthreads();

        // prefetch stage it+NSTAGE-1
        const int pre = it + NSTAGE - 1;
        if (pre < ITERS) {
            const uint32_t st = sb + (pre % NSTAGE) * STAGE_SZ;
            const int k0 = pre * BK;
            cp16(st + cdstA,                 At + csrc + k0);
            cp16(st + cdstA + 64 * ROWB,     At + csrc + (size_t)64 * KDIM + k0);
            cp16(st + A_BYTES + cdstA,       Wt + csrc + k0);
            cp16(st + A_BYTES + cdstA + 64 * ROWB, Wt + csrc + (size_t)64 * KDIM + k0);
        }
        asm volatile("cp.async.commit_group;" ::: "memory");

        // compute stage it
        const uint32_t st = sb + (it % NSTAGE) * STAGE_SZ;
#pragma unroll
        for (int kk = 0; kk < BK; kk += 8) {
            uint32_t a[4][4], b[2][4];
#pragma unroll
            for (int mi = 0; mi < 4; mi++)
                ldsm4(a[mi], st + aoff + mi * (16 * ROWB) + kk * 4);
#pragma unroll
            for (int n2 = 0; n2 < 2; n2++)
                ldsm4(b[n2], st + boff + n2 * (16 * ROWB) + kk * 4);
#pragma unroll
            for (int mi = 0; mi < 4; mi++) {
#pragma unroll
                for (int ni = 0; ni < 4; ni++)
                    mma8(acc[mi][ni], a[mi], b[ni >> 1][(ni & 1) * 2],
                         b[ni >> 1][(ni & 1) * 2 + 1]);
            }
        }
    }

    // ---- epilogue: +bias, relu, tf32-round (intermediate layers), store ----
#pragma unroll
    for (int ni = 0; ni < 4; ni++) {
        const int col = n0 + wn + ni * 8 + 2 * (lane & 3);
        const float bv0 = __ldg(&bias[bz * N + col]);
        const float bv1 = __ldg(&bias[bz * N + col + 1]);
#pragma unroll
        for (int mi = 0; mi < 4; mi++) {
            const size_t r0 = (size_t)(m0g + wm + mi * 16 + (lane >> 2));
            float v0 = acc[mi][ni][0] + bv0;
            float v1 = acc[mi][ni][1] + bv1;
            float v2 = acc[mi][ni][2] + bv0;
            float v3 = acc[mi][ni][3] + bv1;
            if (RELU) {  // relu + rna-round so next layer's tf32 MMA sees rounded operands
                v0 = __uint_as_float(f2tf(fmaxf(v0, 0.0f)));
                v1 = __uint_as_float(f2tf(fmaxf(v1, 0.0f)));
                v2 = __uint_as_float(f2tf(fmaxf(v2, 0.0f)));
                v3 = __uint_as_float(f2tf(fmaxf(v3, 0.0f)));
            }
            *(float2*)(C + r0 * N + col)       = make_float2(v0, v1);
            *(float2*)(C + (r0 + 8) * N + col) = make_float2(v2, v3);
        }
    }
}

// ---------------- tf32 pre-rounding pass ----------------
__global__ void __launch_bounds__(256) round_tf32_kernel(const float4* __restrict__ in,
                                                         float4* __restrict__ out, int n4) {
    const int i = blockIdx.x * blockDim.x + threadIdx.x;
    if (i < n4) {
        float4 v = in[i];
        v.x = __uint_as_float(f2tf(v.x));
        v.y = __uint_as_float(f2tf(v.y));
        v.z = __uint_as_float(f2tf(v.z));
        v.w = __uint_as_float(f2tf(v.w));
        out[i] = v;
    }
}

// ---------------- launch ----------------
extern "C" void kernel_launch(void* const* d_in, const int* in_sizes, int n_in,
                              void* d_out, int out_size) {
    const float* q  = (const float*)d_in[0];
    const float* W0 = (const float*)d_in[1];
    const float* b0 = (const float*)d_in[2];
    const float* W1 = (const float*)d_in[3];
    const float* b1 = (const float*)d_in[4];
    const float* W2 = (const float*)d_in[5];
    const float* b2 = (const float*)d_in[6];
    float* out = (float*)d_out;

    float *qr, *w0, *w1, *w2, *h0, *h1;
    cudaGetSymbolAddress((void**)&qr, g_qr);
    cudaGetSymbolAddress((void**)&w0, g_w0);
    cudaGetSymbolAddress((void**)&w1, g_w1);
    cudaGetSymbolAddress((void**)&w2, g_w2);
    cudaGetSymbolAddress((void**)&h0, g_h0);
    cudaGetSymbolAddress((void**)&h1, g_h1);

    cudaFuncSetAttribute(gemm_tf32_ldsm<512, true>,
                         cudaFuncAttributeMaxDynamicSharedMemorySize, SMEM_BYTES);
    cudaFuncSetAttribute(gemm_tf32_ldsm<1024, true>,
                         cudaFuncAttributeMaxDynamicSharedMemorySize, SMEM_BYTES);
    cudaFuncSetAttribute(gemm_tf32_ldsm<1024, false>,
                         cudaFuncAttributeMaxDynamicSharedMemorySize, SMEM_BYTES);

    // pre-round operands to tf32 (rna)
    {
        int n4;
        n4 = 8 * 4096 * 512 / 4;
        round_tf32_kernel<<<(n4 + 255) / 256, 256>>>((const float4*)q, (float4*)qr, n4);
        n4 = 8 * 1024 * 512 / 4;
        round_tf32_kernel<<<(n4 + 255) / 256, 256>>>((const float4*)W0, (float4*)w0, n4);
        n4 = 8 * 1024 * 1024 / 4;
        round_tf32_kernel<<<(n4 + 255) / 256, 256>>>((const float4*)W1, (float4*)w1, n4);
        n4 = 8 * 512 * 1024 / 4;
        round_tf32_kernel<<<(n4 + 255) / 256, 256>>>((const float4*)W2, (float4*)w2, n4);
    }

    // L0: h0 = relu(q @ W0^T + b0)      M=4096 N=1024 K=512
    {
        dim3 grid(4096 / BM, 1024 / BN, 8);
        gemm_tf32_ldsm<512, true><<<grid, 256, SMEM_BYTES>>>(qr, w0, b0, h0, 1024);
    }
    // L1: h1 = relu(h0 @ W1^T + b1)     M=4096 N=1024 K=1024
    {
        dim3 grid(4096 / BM, 1024 / BN, 8);
        gemm_tf32_ldsm<1024, true><<<grid, 256, SMEM_BYTES>>>(h0, w1, b1, h1, 1024);
    }
    // L2: out = h1 @ W2^T + b2          M=4096 N=512 K=1024
    {
        dim3 grid(4096 / BM, 512 / BN, 8);
        gemm_tf32_ldsm<1024, false><<<grid, 256, SMEM_BYTES>>>(h1, w2, b2, out, 512);
    }
}